// round 2
// baseline (speedup 1.0000x reference)
#include <cuda_runtime.h>
#include <cstdint>

// Problem constants (fixed dataset): N=16384 nodes, E=8192 edges, D=128.
static constexpr int NN = 16384;
static constexpr int NE = 8192;
static constexpr int D  = 128;
static constexpr int WR = NE / 32;   // 256 words per node row  (row-major bits)
static constexpr int WC = NN / 32;   // 512 words per edge col  (col-major bits)

// Scratch (static __device__ — no allocations allowed).
__device__ uint32_t g_bits_r[(size_t)NN * WR];   // 16 MB : bit(n,e) indexed [n][e/32]
__device__ uint32_t g_bits_c[(size_t)NE * WC];   // 16 MB : bit(n,e) indexed [e][n/32]
__device__ float    g_dvih[NN];                  // D_v^{-1/2}
__device__ float    g_dei[NE];                   // D_e^{-1}
__device__ float    g_y2[(size_t)NE * D];        // dei * (H^T (dvih*x))
__device__ float    g_z2[(size_t)NE * D];        // g_y2 @ W^T

// ---------------------------------------------------------------------------
// K1: pack H (512 MB fp32, read once) into row-major and col-major bitmasks.
// Block = 256 threads (8 warps), tile = 256 rows x 256 cols.
// Warp w owns column strip [c0+32w, c0+32w+32); iterates 8 row-bands.
// Row words via ballot over coalesced loads; column words via warp bit-transpose
// (32 more ballots). Both outputs staged in shared and written back in 32B runs.
// ---------------------------------------------------------------------------
__global__ __launch_bounds__(256) void k_pack(const float* __restrict__ H) {
    __shared__ uint32_t sh_r[256][9];   // [local row][word-in-tile], padded
    __shared__ uint32_t sh_c[256][9];   // [local col][band-in-tile], padded
    const int lane = threadIdx.x & 31;
    const int w    = threadIdx.x >> 5;
    const int r0   = blockIdx.y * 256;
    const int c0   = blockIdx.x * 256;

    #pragma unroll 1
    for (int s = 0; s < 8; s++) {
        const float* base = H + (size_t)(r0 + 32 * s) * NE + (c0 + 32 * w);
        uint32_t myrow = 0;
        #pragma unroll
        for (int j = 0; j < 32; j++) {
            float v = base[(size_t)j * NE + lane];           // 128B coalesced
            unsigned word = __ballot_sync(0xffffffffu, v > 0.5f);
            if (lane == j) myrow = word;                      // lane j keeps row j
        }
        sh_r[32 * s + lane][w] = myrow;
        // bit-transpose: column word for col (c0+32w+t) over the 32 rows
        uint32_t mycol = 0;
        #pragma unroll
        for (int t = 0; t < 32; t++) {
            unsigned cw = __ballot_sync(0xffffffffu, (myrow >> t) & 1u);
            if (lane == t) mycol = cw;
        }
        sh_c[32 * w + lane][s] = mycol;
    }
    __syncthreads();
    // coalesced 32B-run writeback
    for (int i = threadIdx.x; i < 2048; i += 256) {
        int row = i >> 3, wc = i & 7;
        g_bits_r[(size_t)(r0 + row) * WR + (c0 >> 5) + wc] = sh_r[row][wc];
    }
    for (int i = threadIdx.x; i < 2048; i += 256) {
        int col = i >> 3, band = i & 7;
        g_bits_c[(size_t)(c0 + col) * WC + (r0 >> 5) + band] = sh_c[col][band];
    }
}

// ---------------------------------------------------------------------------
// K2: degrees + scalings from popcounts (deterministic, no atomics).
// One warp per row/col.
// ---------------------------------------------------------------------------
__global__ __launch_bounds__(256) void k_deg_node() {
    int warp = (blockIdx.x * blockDim.x + threadIdx.x) >> 5;
    int lane = threadIdx.x & 31;
    if (warp >= NN) return;
    const uint32_t* p = g_bits_r + (size_t)warp * WR;
    int s = 0;
    #pragma unroll
    for (int k = 0; k < WR / 32; k++) s += __popc(p[lane + 32 * k]);
    #pragma unroll
    for (int o = 16; o; o >>= 1) s += __shfl_xor_sync(0xffffffffu, s, o);
    if (lane == 0) g_dvih[warp] = (s > 0) ? rsqrtf((float)s) : 0.0f;
}

__global__ __launch_bounds__(256) void k_deg_edge() {
    int warp = (blockIdx.x * blockDim.x + threadIdx.x) >> 5;
    int lane = threadIdx.x & 31;
    if (warp >= NE) return;
    const uint32_t* p = g_bits_c + (size_t)warp * WC;
    int s = 0;
    #pragma unroll
    for (int k = 0; k < WC / 32; k++) s += __popc(p[lane + 32 * k]);
    #pragma unroll
    for (int o = 16; o; o >>= 1) s += __shfl_xor_sync(0xffffffffu, s, o);
    if (lane == 0) g_dei[warp] = (s > 0) ? (1.0f / (float)s) : 0.0f;
}

// ---------------------------------------------------------------------------
// K3: y2[e][d] = dei[e] * sum_{n in edge e} dvih[n] * x[n][d]
// Block = one edge, 128 threads (thread = column d).
// Bits scanned in 4 chunks of 128 words; indices compacted into shared via
// block prefix-scan (preserves ascending-n order -> deterministic fp32 sums).
// ---------------------------------------------------------------------------
__global__ __launch_bounds__(128) void k_edge_gather(const float* __restrict__ x) {
    __shared__ int s_idx[4096];     // worst-case full chunk
    __shared__ int s_wsum[4];
    const int e = blockIdx.x;
    const int tid = threadIdx.x;
    const int lane = tid & 31, wid = tid >> 5;
    const uint32_t* bits = g_bits_c + (size_t)e * WC;
    float acc = 0.0f;
    #pragma unroll 1
    for (int chunk = 0; chunk < 4; chunk++) {
        uint32_t word = bits[chunk * 128 + tid];
        int cnt = __popc(word);
        int v = cnt;
        #pragma unroll
        for (int o = 1; o < 32; o <<= 1) {
            int t = __shfl_up_sync(0xffffffffu, v, o);
            if (lane >= o) v += t;
        }
        if (lane == 31) s_wsum[wid] = v;
        __syncthreads();
        int base = 0;
        #pragma unroll
        for (int k = 0; k < 4; k++) if (k < wid) base += s_wsum[k];
        const int tot = s_wsum[0] + s_wsum[1] + s_wsum[2] + s_wsum[3];
        int pos = base + v - cnt;
        const int nbase = (chunk * 128 + tid) * 32;
        while (word) {
            int bpos = __ffs(word) - 1;
            word &= word - 1;
            s_idx[pos++] = nbase + bpos;
        }
        __syncthreads();
        for (int i = 0; i < tot; i++) {
            int n = s_idx[i];                        // LDS broadcast
            acc += g_dvih[n] * __ldg(&x[(size_t)n * D + tid]);  // x L2-resident
        }
        __syncthreads();
    }
    g_y2[(size_t)e * D + tid] = g_dei[e] * acc;
}

// ---------------------------------------------------------------------------
// K4: z2 = y2 @ W^T   ([8192,128] x [128,128]^T), fp32 tiled GEMM.
// Fold of the final projection onto the E-side (half the rows of the N-side).
// ---------------------------------------------------------------------------
__global__ __launch_bounds__(256) void k_gemm(const float* __restrict__ W) {
    __shared__ float As[64][32];
    __shared__ float Ws[32][129];
    const int tid = threadIdx.x;
    const int tx = tid & 15;      // 16 column tiles x 8
    const int ty = tid >> 4;      // 16 row tiles x 4
    const int m0 = blockIdx.x * 64;
    float acc[4][8];
    #pragma unroll
    for (int i = 0; i < 4; i++)
        #pragma unroll
        for (int j = 0; j < 8; j++) acc[i][j] = 0.0f;

    for (int kk = 0; kk < 128; kk += 32) {
        #pragma unroll
        for (int i = 0; i < 8; i++) {
            int idx = tid + i * 256;              // 0..2047
            int r = idx >> 5, c = idx & 31;
            As[r][c] = g_y2[(size_t)(m0 + r) * 128 + kk + c];
        }
        #pragma unroll
        for (int i = 0; i < 16; i++) {
            int idx = tid + i * 256;              // 0..4095
            int k = idx & 31, n2 = idx >> 5;
            Ws[k][n2] = W[(size_t)n2 * 128 + kk + k];   // coalesced over k
        }
        __syncthreads();
        #pragma unroll
        for (int k = 0; k < 32; k++) {
            float a[4], wv[8];
            #pragma unroll
            for (int i = 0; i < 4; i++) a[i] = As[ty * 4 + i][k];
            #pragma unroll
            for (int j = 0; j < 8; j++) wv[j] = Ws[k][tx * 8 + j];
            #pragma unroll
            for (int i = 0; i < 4; i++)
                #pragma unroll
                for (int j = 0; j < 8; j++) acc[i][j] += a[i] * wv[j];
        }
        __syncthreads();
    }
    #pragma unroll
    for (int i = 0; i < 4; i++)
        #pragma unroll
        for (int j = 0; j < 8; j++)
            g_z2[(size_t)(m0 + ty * 4 + i) * 128 + tx * 8 + j] = acc[i][j];
}

// ---------------------------------------------------------------------------
// K5: out[n][d] = dvih[n] * sum_{e ni n} z2[e][d] + b[d]
// Block = one node, 128 threads. z2 (4 MB) L2-resident.
// ---------------------------------------------------------------------------
__global__ __launch_bounds__(128) void k_node_gather(const float* __restrict__ bvec,
                                                     float* __restrict__ out) {
    __shared__ int s_idx[4096];
    __shared__ int s_wsum[4];
    const int n = blockIdx.x;
    const int tid = threadIdx.x;
    const int lane = tid & 31, wid = tid >> 5;
    const uint32_t* bits = g_bits_r + (size_t)n * WR;
    float acc = 0.0f;
    #pragma unroll 1
    for (int chunk = 0; chunk < 2; chunk++) {
        uint32_t word = bits[chunk * 128 + tid];
        int cnt = __popc(word);
        int v = cnt;
        #pragma unroll
        for (int o = 1; o < 32; o <<= 1) {
            int t = __shfl_up_sync(0xffffffffu, v, o);
            if (lane >= o) v += t;
        }
        if (lane == 31) s_wsum[wid] = v;
        __syncthreads();
        int base = 0;
        #pragma unroll
        for (int k = 0; k < 4; k++) if (k < wid) base += s_wsum[k];
        const int tot = s_wsum[0] + s_wsum[1] + s_wsum[2] + s_wsum[3];
        int pos = base + v - cnt;
        const int ebase = (chunk * 128 + tid) * 32;
        while (word) {
            int bpos = __ffs(word) - 1;
            word &= word - 1;
            s_idx[pos++] = ebase + bpos;
        }
        __syncthreads();
        for (int i = 0; i < tot; i++) {
            int e = s_idx[i];
            acc += __ldg(&g_z2[(size_t)e * D + tid]);
        }
        __syncthreads();
    }
    out[(size_t)n * D + tid] = g_dvih[n] * acc + bvec[tid];
}

// ---------------------------------------------------------------------------
extern "C" void kernel_launch(void* const* d_in, const int* in_sizes, int n_in,
                              void* d_out, int out_size) {
    const float* x = (const float*)d_in[0];   // [16384, 128]
    const float* H = (const float*)d_in[1];   // [16384, 8192]
    const float* W = (const float*)d_in[2];   // [128, 128]
    const float* b = (const float*)d_in[3];   // [128]
    float* out = (float*)d_out;               // [16384, 128]

    dim3 gp(NE / 256, NN / 256);              // 32 x 64
    k_pack<<<gp, 256>>>(H);
    k_deg_node<<<NN / 8, 256>>>();            // 8 warps per block
    k_deg_edge<<<NE / 8, 256>>>();
    k_edge_gather<<<NE, 128>>>(x);
    k_gemm<<<NE / 64, 256>>>(W);
    k_node_gather<<<NN, 128>>>(b, out);
}

// round 4
// speedup vs baseline: 1.2189x; 1.2189x over previous
#include <cuda_runtime.h>
#include <cstdint>

// Problem constants (fixed dataset): N=16384 nodes, E=8192 edges, D=128.
static constexpr int NN = 16384;
static constexpr int NE = 8192;
static constexpr int D  = 128;
static constexpr int WR = NE / 32;   // 256 words per node row  (row-major bits)
static constexpr int WC = NN / 32;   // 512 words per edge col  (col-major bits)

// Scratch (static __device__ — no allocations allowed).
__device__ uint32_t g_bits_r[(size_t)NN * WR];   // 16 MB : bit(n,e) indexed [n][e/32]
__device__ uint32_t g_bits_c[(size_t)NE * WC];   // 16 MB : bit(n,e) indexed [e][n/32]
__device__ int      g_degn_i[NN];
__device__ int      g_dege_i[NE];
__device__ float    g_dvih[NN];                  // D_v^{-1/2}
__device__ float    g_dei[NE];                   // D_e^{-1}
__device__ float    g_y0[(size_t)NN * D];        // dvih * x
__device__ float    g_y2[(size_t)NE * D];        // dei * (H^T y0)
__device__ float    g_z2[(size_t)NE * D];        // g_y2 @ W^T

// ---------------------------------------------------------------------------
// K0: zero the integer degree counters (re-zeroed every graph replay).
// ---------------------------------------------------------------------------
__global__ void k_zero() {
    int i = blockIdx.x * blockDim.x + threadIdx.x;
    if (i < NN) g_degn_i[i] = 0;
    if (i < NE) g_dege_i[i] = 0;
}

// ---------------------------------------------------------------------------
// K1: pack H (512 MB fp32, read once) into row-major and col-major bitmasks,
// and accumulate integer degrees (deterministic int atomics).
// Block = 256 threads (8 warps), tile = 256 rows x 256 cols.
// ---------------------------------------------------------------------------
__global__ __launch_bounds__(256) void k_pack(const float* __restrict__ H) {
    __shared__ uint32_t sh_r[256][9];   // [local row][word-in-tile], padded
    __shared__ uint32_t sh_c[256][9];   // [local col][band-in-tile], padded
    const int lane = threadIdx.x & 31;
    const int w    = threadIdx.x >> 5;
    const int r0   = blockIdx.y * 256;
    const int c0   = blockIdx.x * 256;

    #pragma unroll 1
    for (int s = 0; s < 8; s++) {
        const float* base = H + (size_t)(r0 + 32 * s) * NE + (c0 + 32 * w);
        uint32_t myrow = 0;
        #pragma unroll
        for (int j = 0; j < 32; j++) {
            float v = base[(size_t)j * NE + lane];           // 128B coalesced
            unsigned word = __ballot_sync(0xffffffffu, v > 0.5f);
            if (lane == j) myrow = word;                      // lane j keeps row j
        }
        sh_r[32 * s + lane][w] = myrow;
        // bit-transpose: column word for col (c0+32w+t) over the 32 rows
        uint32_t mycol = 0;
        #pragma unroll
        for (int t = 0; t < 32; t++) {
            unsigned cw = __ballot_sync(0xffffffffu, (myrow >> t) & 1u);
            if (lane == t) mycol = cw;
        }
        sh_c[32 * w + lane][s] = mycol;
    }
    __syncthreads();
    // coalesced 32B-run writeback
    for (int i = threadIdx.x; i < 2048; i += 256) {
        int row = i >> 3, wc = i & 7;
        g_bits_r[(size_t)(r0 + row) * WR + (c0 >> 5) + wc] = sh_r[row][wc];
    }
    for (int i = threadIdx.x; i < 2048; i += 256) {
        int col = i >> 3, band = i & 7;
        g_bits_c[(size_t)(c0 + col) * WC + (r0 >> 5) + band] = sh_c[col][band];
    }
    // fused degree partials (int atomics -> deterministic)
    {
        int t = threadIdx.x;
        int sr = 0, sc = 0;
        #pragma unroll
        for (int k = 0; k < 8; k++) { sr += __popc(sh_r[t][k]); sc += __popc(sh_c[t][k]); }
        atomicAdd(&g_degn_i[r0 + t], sr);
        atomicAdd(&g_dege_i[c0 + t], sc);
    }
}

// ---------------------------------------------------------------------------
// K2: finalize scalings and pre-scale x:  y0[n] = dvih[n] * x[n].
// Block = one node, 128 threads.
// ---------------------------------------------------------------------------
__global__ __launch_bounds__(128) void k_finalize(const float* __restrict__ x) {
    __shared__ float s_s;
    const int n = blockIdx.x;
    const int tid = threadIdx.x;
    if (tid == 0) {
        int d = g_degn_i[n];
        float v = (d > 0) ? rsqrtf((float)d) : 0.0f;
        g_dvih[n] = v;
        s_s = v;
    }
    if (tid == 1 && n < NE) {
        int d = g_dege_i[n];
        g_dei[n] = (d > 0) ? (1.0f / (float)d) : 0.0f;
    }
    __syncthreads();
    g_y0[(size_t)n * D + tid] = s_s * x[(size_t)n * D + tid];
}

// ---------------------------------------------------------------------------
// K3: y2[e] = dei[e] * sum_{n in e} y0[n]   (float4, 8-warp split).
// Block = one edge, 256 threads. Warp w accumulates list slots {w, w+8, ...};
// partials combined in fixed warp order -> deterministic.
// ---------------------------------------------------------------------------
__global__ __launch_bounds__(256) void k_edge_gather() {
    __shared__ int    s_idx[1024];
    __shared__ int    s_wtot[8];
    __shared__ float4 s_acc[8][32];
    const int e = blockIdx.x;
    const int tid = threadIdx.x;
    const int lane = tid & 31, wid = tid >> 5;
    const uint32_t* bits = g_bits_c + (size_t)e * WC;

    uint32_t w0 = bits[tid], w1 = bits[256 + tid];
    int c0 = __popc(w0), c1 = __popc(w1);
    int packed = c0 | (c1 << 16);          // two scans in one (no carry: sums <= 8192)
    int v = packed;
    #pragma unroll
    for (int o = 1; o < 32; o <<= 1) {
        int t = __shfl_up_sync(0xffffffffu, v, o);
        if (lane >= o) v += t;
    }
    if (lane == 31) s_wtot[wid] = v;
    __syncthreads();
    int wbase = 0, totp = 0;
    #pragma unroll
    for (int k = 0; k < 8; k++) { int tk = s_wtot[k]; if (k < wid) wbase += tk; totp += tk; }
    const int tot0 = totp & 0xffff;
    const int tot  = tot0 + (totp >> 16);
    const int excl = wbase + v - packed;
    int p0 = excl & 0xffff;
    int p1 = tot0 + (excl >> 16);
    const int nb0 = tid * 32, nb1 = (256 + tid) * 32;
    while (w0) { int b = __ffs(w0) - 1; w0 &= w0 - 1; s_idx[p0++] = nb0 + b; }
    while (w1) { int b = __ffs(w1) - 1; w1 &= w1 - 1; s_idx[p1++] = nb1 + b; }
    __syncthreads();

    const float4* __restrict__ Y = (const float4*)g_y0;
    float4 acc = make_float4(0.f, 0.f, 0.f, 0.f);
    int i = wid;
    for (; i + 8 < tot; i += 16) {              // 2x unroll -> MLP
        int n0 = s_idx[i], n1 = s_idx[i + 8];
        float4 a = Y[(size_t)n0 * 32 + lane];
        float4 b = Y[(size_t)n1 * 32 + lane];
        acc.x += a.x; acc.y += a.y; acc.z += a.z; acc.w += a.w;
        acc.x += b.x; acc.y += b.y; acc.z += b.z; acc.w += b.w;
    }
    for (; i < tot; i += 8) {
        int n0 = s_idx[i];
        float4 a = Y[(size_t)n0 * 32 + lane];
        acc.x += a.x; acc.y += a.y; acc.z += a.z; acc.w += a.w;
    }
    s_acc[wid][lane] = acc;
    __syncthreads();
    if (wid == 0) {
        float4 r = s_acc[0][lane];
        #pragma unroll
        for (int ww = 1; ww < 8; ww++) {
            float4 a = s_acc[ww][lane];
            r.x += a.x; r.y += a.y; r.z += a.z; r.w += a.w;
        }
        float de = g_dei[e];
        r.x *= de; r.y *= de; r.z *= de; r.w *= de;
        ((float4*)g_y2)[(size_t)e * 32 + lane] = r;
    }
}

// ---------------------------------------------------------------------------
// K4: z2 = y2 @ W^T   ([8192,128] x [128,128]^T), fp32 tiled GEMM.
// ---------------------------------------------------------------------------
__global__ __launch_bounds__(256) void k_gemm(const float* __restrict__ W) {
    __shared__ float As[64][32];
    __shared__ float Ws[32][129];
    const int tid = threadIdx.x;
    const int tx = tid & 15;
    const int ty = tid >> 4;
    const int m0 = blockIdx.x * 64;
    float acc[4][8];
    #pragma unroll
    for (int i = 0; i < 4; i++)
        #pragma unroll
        for (int j = 0; j < 8; j++) acc[i][j] = 0.0f;

    for (int kk = 0; kk < 128; kk += 32) {
        #pragma unroll
        for (int i = 0; i < 8; i++) {
            int idx = tid + i * 256;
            int r = idx >> 5, c = idx & 31;
            As[r][c] = g_y2[(size_t)(m0 + r) * 128 + kk + c];
        }
        #pragma unroll
        for (int i = 0; i < 16; i++) {
            int idx = tid + i * 256;
            int k = idx & 31, n2 = idx >> 5;
            Ws[k][n2] = W[(size_t)n2 * 128 + kk + k];
        }
        __syncthreads();
        #pragma unroll
        for (int k = 0; k < 32; k++) {
            float a[4], wv[8];
            #pragma unroll
            for (int i = 0; i < 4; i++) a[i] = As[ty * 4 + i][k];
            #pragma unroll
            for (int j = 0; j < 8; j++) wv[j] = Ws[k][tx * 8 + j];
            #pragma unroll
            for (int i = 0; i < 4; i++)
                #pragma unroll
                for (int j = 0; j < 8; j++) acc[i][j] += a[i] * wv[j];
        }
        __syncthreads();
    }
    #pragma unroll
    for (int i = 0; i < 4; i++)
        #pragma unroll
        for (int j = 0; j < 8; j++)
            g_z2[(size_t)(m0 + ty * 4 + i) * 128 + tx * 8 + j] = acc[i][j];
}

// ---------------------------------------------------------------------------
// K5: out[n] = dvih[n] * sum_{e ni n} z2[e] + b   (float4, 8-warp split).
// Block = one node, 256 threads (bits: exactly 1 word per thread).
// ---------------------------------------------------------------------------
__global__ __launch_bounds__(256) void k_node_gather(const float* __restrict__ bvec,
                                                     float* __restrict__ out) {
    __shared__ int    s_idx[1024];
    __shared__ int    s_wtot[8];
    __shared__ float4 s_acc[8][32];
    const int n = blockIdx.x;
    const int tid = threadIdx.x;
    const int lane = tid & 31, wid = tid >> 5;
    const uint32_t* bits = g_bits_r + (size_t)n * WR;

    uint32_t w0 = bits[tid];
    int c0 = __popc(w0);
    int v = c0;
    #pragma unroll
    for (int o = 1; o < 32; o <<= 1) {
        int t = __shfl_up_sync(0xffffffffu, v, o);
        if (lane >= o) v += t;
    }
    if (lane == 31) s_wtot[wid] = v;
    __syncthreads();
    int wbase = 0, tot = 0;
    #pragma unroll
    for (int k = 0; k < 8; k++) { int tk = s_wtot[k]; if (k < wid) wbase += tk; tot += tk; }
    int p = wbase + v - c0;
    const int eb = tid * 32;
    while (w0) { int b = __ffs(w0) - 1; w0 &= w0 - 1; s_idx[p++] = eb + b; }
    __syncthreads();

    const float4* __restrict__ Z = (const float4*)g_z2;
    float4 acc = make_float4(0.f, 0.f, 0.f, 0.f);
    int i = wid;
    for (; i + 8 < tot; i += 16) {
        int e0 = s_idx[i], e1 = s_idx[i + 8];
        float4 a = Z[(size_t)e0 * 32 + lane];
        float4 b = Z[(size_t)e1 * 32 + lane];
        acc.x += a.x; acc.y += a.y; acc.z += a.z; acc.w += a.w;
        acc.x += b.x; acc.y += b.y; acc.z += b.z; acc.w += b.w;
    }
    for (; i < tot; i += 8) {
        int e0 = s_idx[i];
        float4 a = Z[(size_t)e0 * 32 + lane];
        acc.x += a.x; acc.y += a.y; acc.z += a.z; acc.w += a.w;
    }
    s_acc[wid][lane] = acc;
    __syncthreads();
    if (wid == 0) {
        float4 r = s_acc[0][lane];
        #pragma unroll
        for (int ww = 1; ww < 8; ww++) {
            float4 a = s_acc[ww][lane];
            r.x += a.x; r.y += a.y; r.z += a.z; r.w += a.w;
        }
        float dv = g_dvih[n];
        float4 bb = ((const float4*)bvec)[lane];
        r.x = r.x * dv + bb.x; r.y = r.y * dv + bb.y;
        r.z = r.z * dv + bb.z; r.w = r.w * dv + bb.w;
        ((float4*)out)[(size_t)n * 32 + lane] = r;
    }
}

// ---------------------------------------------------------------------------
extern "C" void kernel_launch(void* const* d_in, const int* in_sizes, int n_in,
                              void* d_out, int out_size) {
    const float* x = (const float*)d_in[0];   // [16384, 128]
    const float* H = (const float*)d_in[1];   // [16384, 8192]
    const float* W = (const float*)d_in[2];   // [128, 128]
    const float* b = (const float*)d_in[3];   // [128]
    float* out = (float*)d_out;               // [16384, 128]

    k_zero<<<NN / 256, 256>>>();
    dim3 gp(NE / 256, NN / 256);              // 32 x 64
    k_pack<<<gp, 256>>>(H);
    k_finalize<<<NN, 128>>>(x);
    k_edge_gather<<<NE, 256>>>();
    k_gemm<<<NE / 64, 256>>>(W);
    k_node_gather<<<NN, 256>>>(b, out);
}

// round 5
// speedup vs baseline: 1.3025x; 1.0686x over previous
#include <cuda_runtime.h>
#include <cstdint>

// Problem constants (fixed dataset): N=16384 nodes, E=8192 edges, D=128.
static constexpr int NN = 16384;
static constexpr int NE = 8192;
static constexpr int D  = 128;
static constexpr int WR = NE / 32;   // 256 words per node row  (row-major bits)
static constexpr int WC = NN / 32;   // 512 words per edge col  (col-major bits)

// Scratch (static __device__ — no allocations allowed).
// Row-major bit layout is PERMUTED: word gw of row n covers col strip
// (gw>>2)*128, and bit l of word (strip,g) means col = strip*128 + 4*l + g.
// Col-major layout is canonical: word wi of edge e covers nodes [wi*32, wi*32+32),
// bit j -> node wi*32 + j.
__device__ uint32_t g_bits_r[(size_t)NN * WR];   // 16 MB
__device__ uint32_t g_bits_c[(size_t)NE * WC];   // 16 MB
__device__ float    g_y0[(size_t)NN * D];        // dvih * x
__device__ float    g_y2[(size_t)NE * D];        // dei * (H^T y0)
__device__ float    g_z2[(size_t)NE * D];        // g_y2 @ W^T

// ---------------------------------------------------------------------------
// K1: pack H (512 MB fp32, read once) into row-major (permuted) and col-major
// (canonical) bitmasks. Issue-bound -> minimize instructions per 32 bits:
// FSETP + VOTE + @lane0 STS on the row side; LOP + VOTE + @lane0 STS on the
// transpose side, with row words re-read from shared (1 LDS per 32 words).
// Block = 256 threads (8 warps); tile = 256 rows x 256 cols.
// Warp w: col strip cs = w&1 (128 cols), row band rb = w>>3.. (w>>1, 64 rows).
// ---------------------------------------------------------------------------
__global__ __launch_bounds__(256) void k_pack(const float* __restrict__ H) {
    __shared__ uint32_t sh_r[256][9];   // [local row][word 0..7], padded
    __shared__ uint32_t sh_c[256][9];   // [local col][band 0..7], padded
    const int lane = threadIdx.x & 31;
    const int w    = threadIdx.x >> 5;
    const int cs   = w & 1;             // column strip (128 cols)
    const int rb   = w >> 1;            // row band (64 rows)
    const int r0   = blockIdx.y * 256;
    const int c0   = blockIdx.x * 256;
    const int woff = cs * 4;
    const int cbase = cs * 128;
    const bool l0 = (lane == 0);

    #pragma unroll
    for (int s = 0; s < 2; s++) {
        const int rlocal = rb * 64 + s * 32;
        const int bi = rb * 2 + s;
        const float4* __restrict__ Hp =
            (const float4*)(H + (size_t)(r0 + rlocal) * NE + c0 + cbase) + lane;
        // --- row-side: 32 rows x 128 cols, 4 ballots per row ---
        #pragma unroll
        for (int j = 0; j < 32; j++) {
            float4 v = __ldcs(Hp + (size_t)j * (NE / 4));
            unsigned b0 = __ballot_sync(0xffffffffu, v.x > 0.5f);
            unsigned b1 = __ballot_sync(0xffffffffu, v.y > 0.5f);
            unsigned b2 = __ballot_sync(0xffffffffu, v.z > 0.5f);
            unsigned b3 = __ballot_sync(0xffffffffu, v.w > 0.5f);
            if (l0) {
                sh_r[rlocal + j][woff + 0] = b0;
                sh_r[rlocal + j][woff + 1] = b1;
                sh_r[rlocal + j][woff + 2] = b2;
                sh_r[rlocal + j][woff + 3] = b3;
            }
        }
        __syncwarp();
        // --- transpose: read row words back (conflict-free, stride 9), ballot
        // per column. Col (cbase + 4l + g), band bi, bit j = row rlocal + j. ---
        #pragma unroll
        for (int g = 0; g < 4; g++) {
            uint32_t rw = sh_r[rlocal + lane][woff + g];
            #pragma unroll
            for (int l = 0; l < 32; l++) {
                unsigned cw = __ballot_sync(0xffffffffu, (rw & (1u << l)) != 0u);
                if (l0) sh_c[cbase + 4 * l + g][bi] = cw;
            }
        }
        __syncwarp();
    }
    __syncthreads();
    // coalesced 32B-run writeback
    for (int i = threadIdx.x; i < 2048; i += 256) {
        int row = i >> 3, wc = i & 7;
        g_bits_r[(size_t)(r0 + row) * WR + (c0 >> 5) + wc] = sh_r[row][wc];
    }
    for (int i = threadIdx.x; i < 2048; i += 256) {
        int col = i >> 3, band = i & 7;
        g_bits_c[(size_t)(c0 + col) * WC + (r0 >> 5) + band] = sh_c[col][band];
    }
}

// ---------------------------------------------------------------------------
// K2: degree from own row bits (L2-hot), then y0[n] = dvih[n] * x[n].
// Block = one node, 128 threads. No atomics, no zero pass.
// ---------------------------------------------------------------------------
__global__ __launch_bounds__(128) void k_finalize(const float* __restrict__ x) {
    __shared__ int   s_part[4];
    __shared__ float s_s;
    const int n = blockIdx.x;
    const int tid = threadIdx.x;
    const int lane = tid & 31, wid = tid >> 5;
    const uint32_t* bits = g_bits_r + (size_t)n * WR;
    int c = __popc(bits[tid]) + __popc(bits[tid + 128]);
    #pragma unroll
    for (int o = 16; o; o >>= 1) c += __shfl_xor_sync(0xffffffffu, c, o);
    if (lane == 0) s_part[wid] = c;
    __syncthreads();
    if (tid == 0) {
        int d = s_part[0] + s_part[1] + s_part[2] + s_part[3];
        s_s = (d > 0) ? rsqrtf((float)d) : 0.0f;
    }
    __syncthreads();
    g_y0[(size_t)n * D + tid] = s_s * x[(size_t)n * D + tid];
}

// ---------------------------------------------------------------------------
// K3: y2[e] = (1/deg_e) * sum_{n in e} y0[n]   (float4, 8-warp split).
// Canonical col bits: word wi covers nodes [wi*32, wi*32+32).
// ---------------------------------------------------------------------------
__global__ __launch_bounds__(256) void k_edge_gather() {
    __shared__ int    s_idx[1024];
    __shared__ int    s_wtot[8];
    __shared__ float4 s_acc[8][32];
    const int e = blockIdx.x;
    const int tid = threadIdx.x;
    const int lane = tid & 31, wid = tid >> 5;
    const uint32_t* bits = g_bits_c + (size_t)e * WC;

    uint32_t w0 = bits[tid], w1 = bits[256 + tid];
    int c0 = __popc(w0), c1 = __popc(w1);
    int packed = c0 | (c1 << 16);          // two scans in one (no carry: sums <= 16384)
    int v = packed;
    #pragma unroll
    for (int o = 1; o < 32; o <<= 1) {
        int t = __shfl_up_sync(0xffffffffu, v, o);
        if (lane >= o) v += t;
    }
    if (lane == 31) s_wtot[wid] = v;
    __syncthreads();
    int wbase = 0, totp = 0;
    #pragma unroll
    for (int k = 0; k < 8; k++) { int tk = s_wtot[k]; if (k < wid) wbase += tk; totp += tk; }
    const int tot0 = totp & 0xffff;
    const int tot  = tot0 + (totp >> 16);
    const int excl = wbase + v - packed;
    int p0 = excl & 0xffff;
    int p1 = tot0 + (excl >> 16);
    const int nb0 = tid * 32, nb1 = (256 + tid) * 32;
    while (w0) { int b = __ffs(w0) - 1; w0 &= w0 - 1; s_idx[p0++] = nb0 + b; }
    while (w1) { int b = __ffs(w1) - 1; w1 &= w1 - 1; s_idx[p1++] = nb1 + b; }
    __syncthreads();

    const float4* __restrict__ Y = (const float4*)g_y0;
    float4 acc = make_float4(0.f, 0.f, 0.f, 0.f);
    int i = wid;
    for (; i + 8 < tot; i += 16) {              // 2x unroll -> MLP
        int n0 = s_idx[i], n1 = s_idx[i + 8];
        float4 a = Y[(size_t)n0 * 32 + lane];
        float4 b = Y[(size_t)n1 * 32 + lane];
        acc.x += a.x; acc.y += a.y; acc.z += a.z; acc.w += a.w;
        acc.x += b.x; acc.y += b.y; acc.z += b.z; acc.w += b.w;
    }
    for (; i < tot; i += 8) {
        int n0 = s_idx[i];
        float4 a = Y[(size_t)n0 * 32 + lane];
        acc.x += a.x; acc.y += a.y; acc.z += a.z; acc.w += a.w;
    }
    s_acc[wid][lane] = acc;
    __syncthreads();
    if (wid == 0) {
        float4 r = s_acc[0][lane];
        #pragma unroll
        for (int ww = 1; ww < 8; ww++) {
            float4 a = s_acc[ww][lane];
            r.x += a.x; r.y += a.y; r.z += a.z; r.w += a.w;
        }
        float de = (tot > 0) ? (1.0f / (float)tot) : 0.0f;
        r.x *= de; r.y *= de; r.z *= de; r.w *= de;
        ((float4*)g_y2)[(size_t)e * 32 + lane] = r;
    }
}

// ---------------------------------------------------------------------------
// K4: z2 = y2 @ W^T   ([8192,128] x [128,128]^T), fp32 tiled GEMM.
// ---------------------------------------------------------------------------
__global__ __launch_bounds__(256) void k_gemm(const float* __restrict__ W) {
    __shared__ float As[64][32];
    __shared__ float Ws[32][129];
    const int tid = threadIdx.x;
    const int tx = tid & 15;
    const int ty = tid >> 4;
    const int m0 = blockIdx.x * 64;
    float acc[4][8];
    #pragma unroll
    for (int i = 0; i < 4; i++)
        #pragma unroll
        for (int j = 0; j < 8; j++) acc[i][j] = 0.0f;

    for (int kk = 0; kk < 128; kk += 32) {
        #pragma unroll
        for (int i = 0; i < 8; i++) {
            int idx = tid + i * 256;
            int r = idx >> 5, c = idx & 31;
            As[r][c] = g_y2[(size_t)(m0 + r) * 128 + kk + c];
        }
        #pragma unroll
        for (int i = 0; i < 16; i++) {
            int idx = tid + i * 256;
            int k = idx & 31, n2 = idx >> 5;
            Ws[k][n2] = W[(size_t)n2 * 128 + kk + k];
        }
        __syncthreads();
        #pragma unroll
        for (int k = 0; k < 32; k++) {
            float a[4], wv[8];
            #pragma unroll
            for (int i = 0; i < 4; i++) a[i] = As[ty * 4 + i][k];
            #pragma unroll
            for (int j = 0; j < 8; j++) wv[j] = Ws[k][tx * 8 + j];
            #pragma unroll
            for (int i = 0; i < 4; i++)
                #pragma unroll
                for (int j = 0; j < 8; j++) acc[i][j] += a[i] * wv[j];
        }
        __syncthreads();
    }
    #pragma unroll
    for (int i = 0; i < 4; i++)
        #pragma unroll
        for (int j = 0; j < 8; j++)
            g_z2[(size_t)(m0 + ty * 4 + i) * 128 + tx * 8 + j] = acc[i][j];
}

// ---------------------------------------------------------------------------
// K5: out[n] = rsqrt(deg_n) * sum_{e ni n} z2[e] + b   (float4, 8-warp split).
// PERMUTED row bits: word wi, bit b -> edge (wi>>2)*128 + 4*b + (wi&3).
// ---------------------------------------------------------------------------
__global__ __launch_bounds__(256) void k_node_gather(const float* __restrict__ bvec,
                                                     float* __restrict__ out) {
    __shared__ int    s_idx[1024];
    __shared__ int    s_wtot[8];
    __shared__ float4 s_acc[8][32];
    const int n = blockIdx.x;
    const int tid = threadIdx.x;
    const int lane = tid & 31, wid = tid >> 5;
    const uint32_t* bits = g_bits_r + (size_t)n * WR;

    uint32_t w0 = bits[tid];
    int c0 = __popc(w0);
    int v = c0;
    #pragma unroll
    for (int o = 1; o < 32; o <<= 1) {
        int t = __shfl_up_sync(0xffffffffu, v, o);
        if (lane >= o) v += t;
    }
    if (lane == 31) s_wtot[wid] = v;
    __syncthreads();
    int wbase = 0, tot = 0;
    #pragma unroll
    for (int k = 0; k < 8; k++) { int tk = s_wtot[k]; if (k < wid) wbase += tk; tot += tk; }
    int p = wbase + v - c0;
    const int ebase = (tid >> 2) << 7;   // permuted decode
    const int elow  = tid & 3;
    while (w0) { int b = __ffs(w0) - 1; w0 &= w0 - 1; s_idx[p++] = ebase + 4 * b + elow; }
    __syncthreads();

    const float4* __restrict__ Z = (const float4*)g_z2;
    float4 acc = make_float4(0.f, 0.f, 0.f, 0.f);
    int i = wid;
    for (; i + 8 < tot; i += 16) {
        int e0 = s_idx[i], e1 = s_idx[i + 8];
        float4 a = Z[(size_t)e0 * 32 + lane];
        float4 b = Z[(size_t)e1 * 32 + lane];
        acc.x += a.x; acc.y += a.y; acc.z += a.z; acc.w += a.w;
        acc.x += b.x; acc.y += b.y; acc.z += b.z; acc.w += b.w;
    }
    for (; i < tot; i += 8) {
        int e0 = s_idx[i];
        float4 a = Z[(size_t)e0 * 32 + lane];
        acc.x += a.x; acc.y += a.y; acc.z += a.z; acc.w += a.w;
    }
    s_acc[wid][lane] = acc;
    __syncthreads();
    if (wid == 0) {
        float4 r = s_acc[0][lane];
        #pragma unroll
        for (int ww = 1; ww < 8; ww++) {
            float4 a = s_acc[ww][lane];
            r.x += a.x; r.y += a.y; r.z += a.z; r.w += a.w;
        }
        float dv = (tot > 0) ? rsqrtf((float)tot) : 0.0f;
        float4 bb = ((const float4*)bvec)[lane];
        r.x = r.x * dv + bb.x; r.y = r.y * dv + bb.y;
        r.z = r.z * dv + bb.z; r.w = r.w * dv + bb.w;
        ((float4*)out)[(size_t)n * 32 + lane] = r;
    }
}

// ---------------------------------------------------------------------------
extern "C" void kernel_launch(void* const* d_in, const int* in_sizes, int n_in,
                              void* d_out, int out_size) {
    const float* x = (const float*)d_in[0];   // [16384, 128]
    const float* H = (const float*)d_in[1];   // [16384, 8192]
    const float* W = (const float*)d_in[2];   // [128, 128]
    const float* b = (const float*)d_in[3];   // [128]
    float* out = (float*)d_out;               // [16384, 128]

    dim3 gp(NE / 256, NN / 256);              // 32 x 64
    k_pack<<<gp, 256>>>(H);
    k_finalize<<<NN, 128>>>(x);
    k_edge_gather<<<NE, 256>>>();
    k_gemm<<<NE / 64, 256>>>(W);
    k_node_gather<<<NN, 256>>>(b, out);
}

// round 6
// speedup vs baseline: 1.3322x; 1.0228x over previous
#include <cuda_runtime.h>
#include <cuda_fp16.h>
#include <cstdint>

// Problem constants (fixed dataset): N=16384 nodes, E=8192 edges, D=128.
static constexpr int NN = 16384;
static constexpr int NE = 8192;
static constexpr int D  = 128;
static constexpr int WR = NE / 32;   // 256 words per node row  (row-major bits)
static constexpr int WC = NN / 32;   // 512 words per edge col  (col-major bits)

// Bit layouts:
//  row-major (g_bits_r) PERMUTED: word wi of node n covers col strip (wi>>2)*128,
//    bit b of word (strip, g=wi&3) -> col = strip*128 + 4*b + g.
//  col-major (g_bits_c) canonical: word wi of edge e covers nodes [wi*32, wi*32+32),
//    bit j -> node wi*32 + j.
__device__ uint32_t g_bits_r[(size_t)NN * WR];   // 16 MB
__device__ uint32_t g_bits_c[(size_t)NE * WC];   // 16 MB
__device__ __half2  g_y0h[(size_t)NN * (D / 2)]; // dvih * x, fp16 (4 MB)
__device__ float    g_y2[(size_t)NE * D];        // dei * (H^T y0)
__device__ float    g_z2[(size_t)NE * D];        // g_y2 @ W^T

// ---------------------------------------------------------------------------
// 32x32 bit-matrix transpose across a warp (butterfly, 5 stages).
// Input: a[lane] bit l.  Output: a'[lane=l] bit r = a[r] bit l.
// ---------------------------------------------------------------------------
__device__ __forceinline__ uint32_t warp_bit_transpose(uint32_t a, int lane) {
    {   const uint32_t m = 0x0000FFFFu; unsigned p = __shfl_xor_sync(~0u, a, 16);
        a = (lane & 16) ? ((a & ~m) | ((p >> 16) & m)) : ((a & m) | ((p << 16) & ~m)); }
    {   const uint32_t m = 0x00FF00FFu; unsigned p = __shfl_xor_sync(~0u, a, 8);
        a = (lane & 8)  ? ((a & ~m) | ((p >> 8)  & m)) : ((a & m) | ((p << 8)  & ~m)); }
    {   const uint32_t m = 0x0F0F0F0Fu; unsigned p = __shfl_xor_sync(~0u, a, 4);
        a = (lane & 4)  ? ((a & ~m) | ((p >> 4)  & m)) : ((a & m) | ((p << 4)  & ~m)); }
    {   const uint32_t m = 0x33333333u; unsigned p = __shfl_xor_sync(~0u, a, 2);
        a = (lane & 2)  ? ((a & ~m) | ((p >> 2)  & m)) : ((a & m) | ((p << 2)  & ~m)); }
    {   const uint32_t m = 0x55555555u; unsigned p = __shfl_xor_sync(~0u, a, 1);
        a = (lane & 1)  ? ((a & ~m) | ((p >> 1)  & m)) : ((a & m) | ((p << 1)  & ~m)); }
    return a;
}

// ---------------------------------------------------------------------------
// K1: pack H (512 MB fp32, read once) into both bitmask directions.
// Row side: float4 load + 4 ballots + @lane0 STS.
// Col side: warp bit-transpose of row words (1 LDS + ~25 ALU + 1 STS per 32
// output words), stored g-grouped (lane-stride-9 STS: conflict-free),
// un-permuted by index math at writeback. Block = 256 thr; tile 256x256.
// ---------------------------------------------------------------------------
__global__ __launch_bounds__(256) void k_pack(const float* __restrict__ H) {
    __shared__ uint32_t sh_r[256][9];   // [local row][word 0..7], pad
    __shared__ uint32_t sh_c[256][9];   // [cs*128 + g*32 + l][band]; col = cs*128+4l+g
    const int lane = threadIdx.x & 31;
    const int w    = threadIdx.x >> 5;
    const int cs   = w & 1;             // column strip (128 cols)
    const int rb   = w >> 1;            // row band (64 rows)
    const int r0   = blockIdx.y * 256;
    const int c0   = blockIdx.x * 256;
    const int woff = cs * 4;
    const bool l0 = (lane == 0);

    #pragma unroll
    for (int s = 0; s < 2; s++) {
        const int rlocal = rb * 64 + s * 32;
        const int bi = rb * 2 + s;
        const float4* __restrict__ Hp =
            (const float4*)(H + (size_t)(r0 + rlocal) * NE + c0 + cs * 128) + lane;
        #pragma unroll
        for (int j = 0; j < 32; j++) {
            float4 v = __ldcs(Hp + (size_t)j * (NE / 4));
            unsigned b0 = __ballot_sync(~0u, v.x > 0.5f);
            unsigned b1 = __ballot_sync(~0u, v.y > 0.5f);
            unsigned b2 = __ballot_sync(~0u, v.z > 0.5f);
            unsigned b3 = __ballot_sync(~0u, v.w > 0.5f);
            if (l0) {
                sh_r[rlocal + j][woff + 0] = b0;
                sh_r[rlocal + j][woff + 1] = b1;
                sh_r[rlocal + j][woff + 2] = b2;
                sh_r[rlocal + j][woff + 3] = b3;
            }
        }
        __syncwarp();
        #pragma unroll
        for (int g = 0; g < 4; g++) {
            uint32_t a = sh_r[rlocal + lane][woff + g];   // row `lane`, word g
            a = warp_bit_transpose(a, lane);              // col 4*lane+g, bit = row
            sh_c[cs * 128 + g * 32 + lane][bi] = a;
        }
        __syncwarp();
    }
    __syncthreads();
    // coalesced 32B-run writeback
    for (int i = threadIdx.x; i < 2048; i += 256) {
        int row = i >> 3, wc = i & 7;
        g_bits_r[(size_t)(r0 + row) * WR + (c0 >> 5) + wc] = sh_r[row][wc];
    }
    for (int i = threadIdx.x; i < 2048; i += 256) {
        int col = i >> 3, band = i & 7;
        int ccs = col >> 7, rem = col & 127;
        int g = rem >> 5, l = rem & 31;
        int actual = (ccs << 7) | (l << 2) | g;           // undo g-grouping
        g_bits_c[(size_t)(c0 + actual) * WC + (r0 >> 5) + band] = sh_c[col][band];
    }
}

// ---------------------------------------------------------------------------
// K2: degree from own row bits (L2-hot), then y0[n] = fp16(dvih[n] * x[n]).
// Block = one node, 128 threads.
// ---------------------------------------------------------------------------
__global__ __launch_bounds__(128) void k_finalize(const float* __restrict__ x) {
    __shared__ int   s_part[4];
    __shared__ float s_s;
    const int n = blockIdx.x;
    const int tid = threadIdx.x;
    const int lane = tid & 31, wid = tid >> 5;
    const uint32_t* bits = g_bits_r + (size_t)n * WR;
    int c = __popc(bits[tid]) + __popc(bits[tid + 128]);
    #pragma unroll
    for (int o = 16; o; o >>= 1) c += __shfl_xor_sync(0xffffffffu, c, o);
    if (lane == 0) s_part[wid] = c;
    __syncthreads();
    if (tid == 0) {
        int d = s_part[0] + s_part[1] + s_part[2] + s_part[3];
        s_s = (d > 0) ? rsqrtf((float)d) : 0.0f;
    }
    __syncthreads();
    if (tid < 64) {
        float2 xv = ((const float2*)x)[(size_t)n * 64 + tid];
        g_y0h[(size_t)n * 64 + tid] = __floats2half2_rn(s_s * xv.x, s_s * xv.y);
    }
}

// ---------------------------------------------------------------------------
// K3: y2[e] = (1/deg_e) * sum_{n in e} y0[n]   (fp16 rows, fp32 accum).
// Block = one edge, 256 threads, 8-warp list split, fixed combine order.
// ---------------------------------------------------------------------------
__global__ __launch_bounds__(256) void k_edge_gather() {
    __shared__ int    s_idx[1024];
    __shared__ int    s_wtot[8];
    __shared__ float4 s_acc[8][32];
    const int e = blockIdx.x;
    const int tid = threadIdx.x;
    const int lane = tid & 31, wid = tid >> 5;
    const uint32_t* bits = g_bits_c + (size_t)e * WC;

    uint32_t w0 = bits[tid], w1 = bits[256 + tid];
    int c0 = __popc(w0), c1 = __popc(w1);
    int packed = c0 | (c1 << 16);
    int v = packed;
    #pragma unroll
    for (int o = 1; o < 32; o <<= 1) {
        int t = __shfl_up_sync(0xffffffffu, v, o);
        if (lane >= o) v += t;
    }
    if (lane == 31) s_wtot[wid] = v;
    __syncthreads();
    int wbase = 0, totp = 0;
    #pragma unroll
    for (int k = 0; k < 8; k++) { int tk = s_wtot[k]; if (k < wid) wbase += tk; totp += tk; }
    const int tot0 = totp & 0xffff;
    const int tot  = tot0 + (totp >> 16);
    const int excl = wbase + v - packed;
    int p0 = excl & 0xffff;
    int p1 = tot0 + (excl >> 16);
    const int nb0 = tid * 32, nb1 = (256 + tid) * 32;
    while (w0) { int b = __ffs(w0) - 1; w0 &= w0 - 1; s_idx[p0++] = nb0 + b; }
    while (w1) { int b = __ffs(w1) - 1; w1 &= w1 - 1; s_idx[p1++] = nb1 + b; }
    __syncthreads();

    const uint2* __restrict__ Y = (const uint2*)g_y0h;   // 4 halves per lane
    float4 acc = make_float4(0.f, 0.f, 0.f, 0.f);
    int i = wid;
    for (; i + 8 < tot; i += 16) {
        int n0 = s_idx[i], n1 = s_idx[i + 8];
        uint2 ua = __ldg(&Y[(size_t)n0 * 32 + lane]);
        uint2 ub = __ldg(&Y[(size_t)n1 * 32 + lane]);
        float2 a0 = __half22float2(*(__half2*)&ua.x);
        float2 a1 = __half22float2(*(__half2*)&ua.y);
        float2 b0 = __half22float2(*(__half2*)&ub.x);
        float2 b1 = __half22float2(*(__half2*)&ub.y);
        acc.x += a0.x; acc.y += a0.y; acc.z += a1.x; acc.w += a1.y;
        acc.x += b0.x; acc.y += b0.y; acc.z += b1.x; acc.w += b1.y;
    }
    for (; i < tot; i += 8) {
        int n0 = s_idx[i];
        uint2 ua = __ldg(&Y[(size_t)n0 * 32 + lane]);
        float2 a0 = __half22float2(*(__half2*)&ua.x);
        float2 a1 = __half22float2(*(__half2*)&ua.y);
        acc.x += a0.x; acc.y += a0.y; acc.z += a1.x; acc.w += a1.y;
    }
    s_acc[wid][lane] = acc;
    __syncthreads();
    if (wid == 0) {
        float4 r = s_acc[0][lane];
        #pragma unroll
        for (int ww = 1; ww < 8; ww++) {
            float4 a = s_acc[ww][lane];
            r.x += a.x; r.y += a.y; r.z += a.z; r.w += a.w;
        }
        float de = (tot > 0) ? (1.0f / (float)tot) : 0.0f;
        r.x *= de; r.y *= de; r.z *= de; r.w *= de;
        ((float4*)g_y2)[(size_t)e * 32 + lane] = r;
    }
}

// ---------------------------------------------------------------------------
// K4: z2 = y2 @ W^T  ([8192,128] x [128,128]^T).
// 256 blocks x 256 threads, tile 32x128, acc 4x4, K chunks of 32.
// A k-major in smem (LDS.128 broadcast); W chunk k-major (LDS.128).
// ---------------------------------------------------------------------------
__global__ __launch_bounds__(256) void k_gemm(const float* __restrict__ W) {
    __shared__ float Ast[32][36];    // [k][row]
    __shared__ float Ws[32][128];    // [k][n]
    const int tid = threadIdx.x;
    const int tx = tid & 31;         // cols tx*4..+3
    const int ty = tid >> 5;         // rows ty*4..+3
    const int m0 = blockIdx.x * 32;
    float acc[4][4];
    #pragma unroll
    for (int i = 0; i < 4; i++)
        #pragma unroll
        for (int j = 0; j < 4; j++) acc[i][j] = 0.0f;

    for (int kk = 0; kk < 128; kk += 32) {
        {   // A chunk: 32 rows x 32 k, transposed into Ast
            int r = tid >> 3;
            int k4 = (tid & 7) * 4;
            float4 vv = *(const float4*)&g_y2[(size_t)(m0 + r) * 128 + kk + k4];
            Ast[k4 + 0][r] = vv.x; Ast[k4 + 1][r] = vv.y;
            Ast[k4 + 2][r] = vv.z; Ast[k4 + 3][r] = vv.w;
        }
        {   // W chunk: Ws[k][n] = W[n][kk+k], 128 n x 32 k
            int n2 = tid >> 1;
            int k8 = (tid & 1) * 16;
            #pragma unroll
            for (int q = 0; q < 4; q++) {
                float4 vv = *(const float4*)&W[(size_t)n2 * 128 + kk + k8 + q * 4];
                Ws[k8 + q * 4 + 0][n2] = vv.x; Ws[k8 + q * 4 + 1][n2] = vv.y;
                Ws[k8 + q * 4 + 2][n2] = vv.z; Ws[k8 + q * 4 + 3][n2] = vv.w;
            }
        }
        __syncthreads();
        #pragma unroll
        for (int k = 0; k < 32; k++) {
            float4 a  = *(const float4*)&Ast[k][ty * 4];   // broadcast
            float4 wv = *(const float4*)&Ws[k][tx * 4];
            acc[0][0] += a.x * wv.x; acc[0][1] += a.x * wv.y; acc[0][2] += a.x * wv.z; acc[0][3] += a.x * wv.w;
            acc[1][0] += a.y * wv.x; acc[1][1] += a.y * wv.y; acc[1][2] += a.y * wv.z; acc[1][3] += a.y * wv.w;
            acc[2][0] += a.z * wv.x; acc[2][1] += a.z * wv.y; acc[2][2] += a.z * wv.z; acc[2][3] += a.z * wv.w;
            acc[3][0] += a.w * wv.x; acc[3][1] += a.w * wv.y; acc[3][2] += a.w * wv.z; acc[3][3] += a.w * wv.w;
        }
        __syncthreads();
    }
    #pragma unroll
    for (int i = 0; i < 4; i++) {
        float4 o = make_float4(acc[i][0], acc[i][1], acc[i][2], acc[i][3]);
        *(float4*)&g_z2[(size_t)(m0 + ty * 4 + i) * 128 + tx * 4] = o;
    }
}

// ---------------------------------------------------------------------------
// K5: out[n] = rsqrt(deg_n) * sum_{e ni n} z2[e] + b   (float4, 8-warp split).
// PERMUTED row bits: word wi, bit b -> edge (wi>>2)*128 + 4*b + (wi&3).
// ---------------------------------------------------------------------------
__global__ __launch_bounds__(256) void k_node_gather(const float* __restrict__ bvec,
                                                     float* __restrict__ out) {
    __shared__ int    s_idx[1024];
    __shared__ int    s_wtot[8];
    __shared__ float4 s_acc[8][32];
    const int n = blockIdx.x;
    const int tid = threadIdx.x;
    const int lane = tid & 31, wid = tid >> 5;
    const uint32_t* bits = g_bits_r + (size_t)n * WR;

    uint32_t w0 = bits[tid];
    int c0 = __popc(w0);
    int v = c0;
    #pragma unroll
    for (int o = 1; o < 32; o <<= 1) {
        int t = __shfl_up_sync(0xffffffffu, v, o);
        if (lane >= o) v += t;
    }
    if (lane == 31) s_wtot[wid] = v;
    __syncthreads();
    int wbase = 0, tot = 0;
    #pragma unroll
    for (int k = 0; k < 8; k++) { int tk = s_wtot[k]; if (k < wid) wbase += tk; tot += tk; }
    int p = wbase + v - c0;
    const int ebase = (tid >> 2) << 7;   // permuted decode
    const int elow  = tid & 3;
    while (w0) { int b = __ffs(w0) - 1; w0 &= w0 - 1; s_idx[p++] = ebase + 4 * b + elow; }
    __syncthreads();

    const float4* __restrict__ Z = (const float4*)g_z2;
    float4 acc = make_float4(0.f, 0.f, 0.f, 0.f);
    int i = wid;
    for (; i + 8 < tot; i += 16) {
        int e0 = s_idx[i], e1 = s_idx[i + 8];
        float4 a = Z[(size_t)e0 * 32 + lane];
        float4 b = Z[(size_t)e1 * 32 + lane];
        acc.x += a.x; acc.y += a.y; acc.z += a.z; acc.w += a.w;
        acc.x += b.x; acc.y += b.y; acc.z += b.z; acc.w += b.w;
    }
    for (; i < tot; i += 8) {
        int e0 = s_idx[i];
        float4 a = Z[(size_t)e0 * 32 + lane];
        acc.x += a.x; acc.y += a.y; acc.z += a.z; acc.w += a.w;
    }
    s_acc[wid][lane] = acc;
    __syncthreads();
    if (wid == 0) {
        float4 r = s_acc[0][lane];
        #pragma unroll
        for (int ww = 1; ww < 8; ww++) {
            float4 a = s_acc[ww][lane];
            r.x += a.x; r.y += a.y; r.z += a.z; r.w += a.w;
        }
        float dv = (tot > 0) ? rsqrtf((float)tot) : 0.0f;
        float4 bb = ((const float4*)bvec)[lane];
        r.x = r.x * dv + bb.x; r.y = r.y * dv + bb.y;
        r.z = r.z * dv + bb.z; r.w = r.w * dv + bb.w;
        ((float4*)out)[(size_t)n * 32 + lane] = r;
    }
}

// ---------------------------------------------------------------------------
extern "C" void kernel_launch(void* const* d_in, const int* in_sizes, int n_in,
                              void* d_out, int out_size) {
    const float* x = (const float*)d_in[0];   // [16384, 128]
    const float* H = (const float*)d_in[1];   // [16384, 8192]
    const float* W = (const float*)d_in[2];   // [128, 128]
    const float* b = (const float*)d_in[3];   // [128]
    float* out = (float*)d_out;               // [16384, 128]

    dim3 gp(NE / 256, NN / 256);              // 32 x 64
    k_pack<<<gp, 256>>>(H);
    k_finalize<<<NN, 128>>>(x);
    k_edge_gather<<<NE, 256>>>();
    k_gemm<<<NE / 32, 256>>>(W);              // 256 blocks, 32-row tiles
    k_node_gather<<<NN, 256>>>(b, out);
}